// round 2
// baseline (speedup 1.0000x reference)
#include <cuda_runtime.h>
#include <math.h>

// Problem constants
#define SRC 2      // 0 = lab, 1 = pred-argmax
#define NB  4
#define NC  3
#define HH  256
#define WW  256
#define NPIX (HH*WW)
#define LIMIT_F 331776.0f   // 576*576
#define NORM_EPS 1e-5f
#define COS_EPS 1e-8f

// Scratch (device globals — no allocation allowed)
__device__ unsigned char g_lbl[SRC][NB][HH][WW];   // per-pixel class label
__device__ float         g_rd [SRC][NB][HH][WW];   // row-pass squared distance (own class)
__device__ float         g_edt[SRC][NB][HH][WW];   // sqrt of full 2D squared EDT (own class)
__device__ unsigned int  g_cmax[SRC][NB][NC];      // per-mask max of edt (float bits)
__device__ float         g_psum[NB][64];           // per-block sim partial sums
__device__ int           g_pfg [NB][64];           // per-block fg-pixel counts

// argmax over C=3 for pred; pack lab to uint8. Block 0 also clears g_cmax
// (safe: g_cmax is only read by k_col, which launches after this kernel).
__global__ void k_argmax(const float* __restrict__ pred, const int* __restrict__ lab) {
    int idx = blockIdx.x * blockDim.x + threadIdx.x;   // 0 .. NB*NPIX-1
    if (blockIdx.x == 0 && threadIdx.x < SRC*NB*NC)
        ((unsigned int*)g_cmax)[threadIdx.x] = 0u;
    int b = idx >> 16;
    int p = idx & 65535;
    const float* pb = pred + (size_t)b * NC * NPIX + p;
    float v0 = pb[0], v1 = pb[NPIX], v2 = pb[2*NPIX];
    int am = 0; float bv = v0;
    if (v1 > bv) { bv = v1; am = 1; }      // strict > matches jnp.argmax first-max tie-break
    if (v2 > bv) { am = 2; }
    ((unsigned char*)g_lbl[1])[idx] = (unsigned char)am;
    ((unsigned char*)g_lbl[0])[idx] = (unsigned char)lab[idx];
}

// Row pass: for each pixel, squared distance (in-row) to nearest different-label pixel.
// One block per (src,b,row); thread j = column. Outward scan, expected ~3 iters.
__global__ void k_row() {
    int bx  = blockIdx.x;           // 0..2047
    int src = bx >> 10;
    int rem = bx & 1023;
    int b   = rem >> 8;
    int i   = rem & 255;
    __shared__ unsigned char s_lb[WW];
    int j = threadIdx.x;
    s_lb[j] = g_lbl[src][b][i][j];
    __syncthreads();
    int c = s_lb[j];
    int dl = 1 << 20;
    for (int k = j - 1; k >= 0; --k)
        if (s_lb[k] != c) { dl = j - k; break; }
    for (int k = j + 1; k < WW; ++k) {
        if (k - j >= dl) break;
        if (s_lb[k] != c) { dl = k - j; break; }
    }
    float r2 = (dl <= 511) ? (float)(dl * dl) : 1e9f;   // 1e9 == reference BIG
    g_rd[src][b][i][j] = r2;
}

// Column pass: exact 1D transform d2(i) = min_k f_c(k) + (i-k)^2 with
// f_c(k) = rd(k) if lbl(k)==c else 0. Outward scan with dominance early-exit
// is exact (all terms beyond break point are >= current best).
__global__ void k_col() {
    int bx  = blockIdx.x;
    int src = bx >> 10;
    int rem = bx & 1023;
    int b   = rem >> 8;
    int j   = rem & 255;
    __shared__ unsigned char s_lb[HH];
    __shared__ float s_rd[HH];
    __shared__ unsigned int smax[NC];
    int i = threadIdx.x;
    s_lb[i] = g_lbl[src][b][i][j];
    s_rd[i] = g_rd[src][b][i][j];
    if (i < NC) smax[i] = 0u;
    __syncthreads();

    int c = s_lb[i];
    float best = s_rd[i];                       // k == i term (own class)
    for (int k = i - 1; k >= 0; --k) {
        int d = i - k;
        float q = (float)(d * d);
        if (q >= best) break;                   // dominated beyond here
        if (s_lb[k] != c) { best = q; break; }  // f=0 candidate; farther ones dominated
        float v = s_rd[k] + q;
        if (v < best) best = v;
    }
    for (int k = i + 1; k < HH; ++k) {
        int d = k - i;
        float q = (float)(d * d);
        if (q >= best) break;
        if (s_lb[k] != c) { best = q; break; }
        float v = s_rd[k] + q;
        if (v < best) best = v;
    }
    float e = sqrtf(best);
    g_edt[src][b][i][j] = e;
    atomicMax(&smax[c], __float_as_uint(e));    // e >= 0: uint order == float order
    __syncthreads();
    if (i < NC) atomicMax(&g_cmax[src][b][i], smax[i]);
}

// Per-pixel cosine similarity of [sum_dw ; onehot] features + deterministic block reduce.
__global__ void k_pix() {
    int b = blockIdx.y;
    int p = blockIdx.x * 1024 + threadIdx.x;
    int cl = ((const unsigned char*)g_lbl[0][b])[p];
    int cp = ((const unsigned char*)g_lbl[1][b])[p];
    float denl = fminf(__uint_as_float(g_cmax[0][b][cl]), LIMIT_F) + NORM_EPS;
    float denp = fminf(__uint_as_float(g_cmax[1][b][cp]), LIMIT_F) + NORM_EPS;
    float sl = ((const float*)g_edt[0][b])[p] / denl;   // sum_c dw == own-class dw
    float sp = ((const float*)g_edt[1][b])[p] / denp;
    float dot = sp * sl + ((cl == cp) ? 1.0f : 0.0f);
    float na = sqrtf(sp * sp + 1.0f);
    float nb = sqrtf(sl * sl + 1.0f);
    float sim = dot / (fmaxf(na, COS_EPS) * fmaxf(nb, COS_EPS));
    int fg = (cl > 0) ? 1 : 0;

    __shared__ float ss[1024];
    __shared__ int   sf[1024];
    int t = threadIdx.x;
    ss[t] = sim; sf[t] = fg;
    __syncthreads();
    for (int o = 512; o > 0; o >>= 1) {
        if (t < o) { ss[t] += ss[t + o]; sf[t] += sf[t + o]; }
        __syncthreads();
    }
    if (t == 0) { g_psum[b][blockIdx.x] = ss[0]; g_pfg[b][blockIdx.x] = sf[0]; }
}

// Deterministic scalar finish.
__global__ void k_final(float* __restrict__ out) {
    double loss = 0.0;
    for (int b = 0; b < NB; ++b) {
        double s = 0.0; int fg = 0;
        for (int k = 0; k < 64; ++k) { s += (double)g_psum[b][k]; fg += g_pfg[b][k]; }
        float lb = 1.0f - (float)(s / 65536.0);
        if (fg > 0) loss += (double)lb;
    }
    float L = (float)(loss / (double)NB);
    if (isnan(L)) L = 0.0f;
    else if (isinf(L)) L = (L > 0.0f) ? 1.0f : 0.0f;
    out[0] = L;
}

extern "C" void kernel_launch(void* const* d_in, const int* in_sizes, int n_in,
                              void* d_out, int out_size) {
    const float* pred;
    const int*   lab;
    // metadata order: pred (4*3*256*256), lab (4*256*256). Defensive size check.
    if (n_in >= 2 && in_sizes[0] == NB*NPIX && in_sizes[1] == NB*NC*NPIX) {
        lab  = (const int*)d_in[0];
        pred = (const float*)d_in[1];
    } else {
        pred = (const float*)d_in[0];
        lab  = (const int*)d_in[1];
    }
    float* out = (float*)d_out;

    k_argmax<<<(NB*NPIX)/256, 256>>>(pred, lab);
    k_row<<<SRC*NB*HH, WW>>>();
    k_col<<<SRC*NB*WW, HH>>>();
    k_pix<<<dim3(64, NB), 1024>>>();
    k_final<<<1, 1>>>(out);
    (void)out_size;
}

// round 3
// speedup vs baseline: 1.7433x; 1.7433x over previous
#include <cuda_runtime.h>
#include <math.h>

#define SRC 2      // 0 = lab, 1 = pred-argmax
#define NB  4
#define NC  3
#define HH  256
#define WW  256
#define NPIX (HH*WW)
#define LIMIT_F 331776.0f   // 576*576
#define NORM_EPS 1e-5f

// Scratch (device globals — no allocation allowed). All big arrays TRANSPOSED: [src][b][j][i]
__device__ unsigned char g_lblT[SRC][NB][WW][HH];
__device__ float         g_rdT [SRC][NB][WW][HH];
__device__ float         g_edtT[SRC][NB][WW][HH];
__device__ unsigned int  g_cmax[SRC][NB][NC];
__device__ float         g_psum[NB][16];
__device__ int           g_pfg [NB][16];
__device__ unsigned int  g_tick;   // zero-init; reset by last K3 block each run

// ---------------------------------------------------------------------------
// K1: fused argmax + label pack + row-pass EDT. One block = 4 rows of batch b.
// Stores labels and row squared-distances TRANSPOSED (uchar4 / float4 per thread).
__global__ void k1(const float* __restrict__ pred, const int* __restrict__ lab) {
    int bx = blockIdx.x;            // 0..255
    int b  = bx >> 6;               // 64 blocks per batch
    int i0 = (bx & 63) << 2;        // first of 4 rows
    int j  = threadIdx.x;
    if (bx == 0 && j < SRC*NB*NC) ((unsigned int*)g_cmax)[j] = 0u;

    __shared__ unsigned char s_lb[SRC][4][WW];
    __shared__ float         s_r2[SRC][4][WW];

    const float* pb = pred + (size_t)b * NC * NPIX + (size_t)i0 * WW + j;
    const int*   lb = lab  + (size_t)b * NPIX      + (size_t)i0 * WW + j;
    #pragma unroll
    for (int r = 0; r < 4; ++r) {
        float v0 = pb[r*WW], v1 = pb[r*WW + NPIX], v2 = pb[r*WW + 2*NPIX];
        int am = 0; float bv = v0;
        if (v1 > bv) { bv = v1; am = 1; }      // strict > == jnp.argmax tie-break
        if (v2 > bv) { am = 2; }
        s_lb[1][r][j] = (unsigned char)am;
        s_lb[0][r][j] = (unsigned char)lb[r*WW];
    }
    __syncthreads();

    #pragma unroll
    for (int s = 0; s < SRC; ++s)
        #pragma unroll
        for (int r = 0; r < 4; ++r) {
            const unsigned char* L = s_lb[s][r];
            int c = L[j];
            int dl = 1 << 20;
            for (int k = j - 1; k >= 0; --k)
                if (L[k] != c) { dl = j - k; break; }
            for (int k = j + 1; k < WW; ++k) {
                if (k - j >= dl) break;
                if (L[k] != c) { dl = k - j; break; }
            }
            s_r2[s][r][j] = (dl <= 511) ? (float)(dl * dl) : 1e9f;  // 1e9 == reference BIG
        }
    __syncthreads();

    #pragma unroll
    for (int s = 0; s < SRC; ++s) {
        uchar4 u = make_uchar4(s_lb[s][0][j], s_lb[s][1][j], s_lb[s][2][j], s_lb[s][3][j]);
        *(uchar4*)&g_lblT[s][b][j][i0] = u;
        float4 f = make_float4(s_r2[s][0][j], s_r2[s][1][j], s_r2[s][2][j], s_r2[s][3][j]);
        *(float4*)&g_rdT[s][b][j][i0] = f;
    }
}

// ---------------------------------------------------------------------------
// K2: column-pass exact 1D transform + per-mask max. One block = 4 columns.
// All loads/stores coalesced (transposed layout). Outward scan with dominance
// early-exit is exact: beyond a break, every candidate f+q' >= current best.
__global__ void k2() {
    int bx = blockIdx.x;            // 0..511
    int s  = bx >> 8;
    int b  = (bx >> 6) & 3;
    int j0 = (bx & 63) << 2;
    int i  = threadIdx.x;

    __shared__ unsigned char s_lb[4][HH];
    __shared__ float         s_rd[4][HH];
    __shared__ unsigned int  smax[NC];
    if (i < NC) smax[i] = 0u;
    #pragma unroll
    for (int q = 0; q < 4; ++q) {
        s_lb[q][i] = g_lblT[s][b][j0 + q][i];
        s_rd[q][i] = g_rdT [s][b][j0 + q][i];
    }
    __syncthreads();

    #pragma unroll
    for (int q = 0; q < 4; ++q) {
        const unsigned char* L = s_lb[q];
        const float*         R = s_rd[q];
        int c = L[i];
        float best = R[i];
        for (int k = i - 1; k >= 0; --k) {
            int d = i - k; float qd = (float)(d * d);
            if (qd >= best) break;
            if (L[k] != c) { best = qd; break; }
            float v = R[k] + qd; if (v < best) best = v;
        }
        for (int k = i + 1; k < HH; ++k) {
            int d = k - i; float qd = (float)(d * d);
            if (qd >= best) break;
            if (L[k] != c) { best = qd; break; }
            float v = R[k] + qd; if (v < best) best = v;
        }
        float e = sqrtf(best);
        g_edtT[s][b][j0 + q][i] = e;
        atomicMax(&smax[c], __float_as_uint(e));   // e >= 0: uint order == float order
    }
    __syncthreads();
    if (i < NC) atomicMax(&g_cmax[s][b][i], smax[i]);
}

// ---------------------------------------------------------------------------
// K3: per-pixel cosine similarity + deterministic two-stage reduce + ticketed
// final combine (last block computes the scalar loss). Pixel order is the
// transposed order — the mean is order-independent, tree order is fixed.
__global__ void k3(float* __restrict__ out) {
    int b = blockIdx.y;
    int t = threadIdx.x;
    __shared__ float s_invl[NC], s_invp[NC];
    __shared__ float wsum[8];
    __shared__ int   wfg[8];
    if (t < NC)
        s_invl[t] = 1.0f / (fminf(__uint_as_float(g_cmax[0][b][t]), LIMIT_F) + NORM_EPS);
    else if (t < 2*NC)
        s_invp[t - NC] = 1.0f / (fminf(__uint_as_float(g_cmax[1][b][t - NC]), LIMIT_F) + NORM_EPS);
    __syncthreads();

    const uchar4* Lc = (const uchar4*)g_lblT[0][b];
    const uchar4* Pc = (const uchar4*)g_lblT[1][b];
    const float4* Le = (const float4*)g_edtT[0][b];
    const float4* Pe = (const float4*)g_edtT[1][b];

    int base = blockIdx.x * 1024;   // in float4 units; 16 blocks cover 16384 f4 = 65536 px
    float acc = 0.0f; int fg = 0;
    #pragma unroll
    for (int u = 0; u < 4; ++u) {
        int v = base + u * 256 + t;
        uchar4 lc = Lc[v], pc = Pc[v];
        float4 le = Le[v], pe = Pe[v];
        {
            float sl = le.x * s_invl[lc.x], sp = pe.x * s_invp[pc.x];
            float dot = sp * sl + ((lc.x == pc.x) ? 1.0f : 0.0f);
            acc += dot * rsqrtf((sp * sp + 1.0f) * (sl * sl + 1.0f));
            fg += (lc.x > 0);
        }
        {
            float sl = le.y * s_invl[lc.y], sp = pe.y * s_invp[pc.y];
            float dot = sp * sl + ((lc.y == pc.y) ? 1.0f : 0.0f);
            acc += dot * rsqrtf((sp * sp + 1.0f) * (sl * sl + 1.0f));
            fg += (lc.y > 0);
        }
        {
            float sl = le.z * s_invl[lc.z], sp = pe.z * s_invp[pc.z];
            float dot = sp * sl + ((lc.z == pc.z) ? 1.0f : 0.0f);
            acc += dot * rsqrtf((sp * sp + 1.0f) * (sl * sl + 1.0f));
            fg += (lc.z > 0);
        }
        {
            float sl = le.w * s_invl[lc.w], sp = pe.w * s_invp[pc.w];
            float dot = sp * sl + ((lc.w == pc.w) ? 1.0f : 0.0f);
            acc += dot * rsqrtf((sp * sp + 1.0f) * (sl * sl + 1.0f));
            fg += (lc.w > 0);
        }
    }

    #pragma unroll
    for (int o = 16; o > 0; o >>= 1) {
        acc += __shfl_down_sync(0xffffffffu, acc, o);
        fg  += __shfl_down_sync(0xffffffffu, fg,  o);
    }
    int w = t >> 5;
    if ((t & 31) == 0) { wsum[w] = acc; wfg[w] = fg; }
    __syncthreads();

    if (t == 0) {
        float ssum = 0.0f; int sf = 0;
        #pragma unroll
        for (int k = 0; k < 8; ++k) { ssum += wsum[k]; sf += wfg[k]; }
        g_psum[b][blockIdx.x] = ssum;
        g_pfg [b][blockIdx.x] = sf;
        __threadfence();
        unsigned int old = atomicAdd(&g_tick, 1u);
        if (old == 63u) {                 // last of 64 blocks
            __threadfence();
            double loss = 0.0;
            for (int bb = 0; bb < NB; ++bb) {
                double s2 = 0.0; int f2 = 0;
                for (int k = 0; k < 16; ++k) { s2 += (double)g_psum[bb][k]; f2 += g_pfg[bb][k]; }
                float lb2 = 1.0f - (float)(s2 / 65536.0);
                if (f2 > 0) loss += (double)lb2;
            }
            float L = (float)(loss / (double)NB);
            if (isnan(L)) L = 0.0f;
            else if (isinf(L)) L = (L > 0.0f) ? 1.0f : 0.0f;
            out[0] = L;
            g_tick = 0u;                  // reset for next graph replay
        }
    }
}

// ---------------------------------------------------------------------------
extern "C" void kernel_launch(void* const* d_in, const int* in_sizes, int n_in,
                              void* d_out, int out_size) {
    const float* pred;
    const int*   lab;
    if (n_in >= 2 && in_sizes[0] == NB*NPIX && in_sizes[1] == NB*NC*NPIX) {
        lab  = (const int*)d_in[0];
        pred = (const float*)d_in[1];
    } else {
        pred = (const float*)d_in[0];
        lab  = (const int*)d_in[1];
    }
    float* out = (float*)d_out;

    k1<<<NB*HH/4, WW>>>(pred, lab);       // 256 blocks x 256 thr
    k2<<<SRC*NB*WW/4, HH>>>();            // 512 blocks x 256 thr
    k3<<<dim3(16, NB), 256>>>(out);       // 64 blocks x 256 thr
    (void)out_size;
}